// round 3
// baseline (speedup 1.0000x reference)
#include <cuda_runtime.h>

#define BATCH 128
#define SITES 256
#define BOND 64
#define NOUT 10
#define HALFS 128   // sites per half

// Scratch (device globals — no allocation allowed)
__device__ float g_ct[HALFS * BOND * BOND * 2]; // right half cores, transposed+reversed: [t][r][2l+i]
__device__ float g_vL[BATCH * BOND];
__device__ float g_wR[BATCH * BOND];

// ---- packed f32x2 helpers (Blackwell full-rate FMA path) ----
static __device__ __forceinline__ unsigned long long ffma2(
    unsigned long long a, unsigned long long b, unsigned long long c) {
    unsigned long long d;
    asm("fma.rn.f32x2 %0, %1, %2, %3;" : "=l"(d) : "l"(a), "l"(b), "l"(c));
    return d;
}
static __device__ __forceinline__ unsigned long long fadd2(
    unsigned long long a, unsigned long long b) {
    unsigned long long d;
    asm("add.rn.f32x2 %0, %1, %2;" : "=l"(d) : "l"(a), "l"(b));
    return d;
}
static __device__ __forceinline__ float f2lo(unsigned long long v) {
    return __uint_as_float((unsigned)(v & 0xffffffffull));
}
static __device__ __forceinline__ float f2hi(unsigned long long v) {
    return __uint_as_float((unsigned)(v >> 32));
}

// ============================================================
// Kernel 1: repack right-half cores.
// g_ct[t][r][2l+i] = cores[255 - t][l][r][i]   (transpose l<->r, reverse site order)
// so the right chain (w' = M w) uses the same column-contiguous code as the left.
// ============================================================
__global__ void __launch_bounds__(256) repack_kernel(const float* __restrict__ cores) {
    int t = blockIdx.x;            // 0..127
    int s = 255 - t;
    __shared__ float2 sh[64 * 65]; // padded to dodge bank conflicts
    const float2* src = (const float2*)cores + (size_t)s * 4096; // [l*64 + r] -> (c0,c1)
    float2* dst = (float2*)g_ct + (size_t)t * 4096;              // [r*64 + l]
    for (int idx = threadIdx.x; idx < 4096; idx += blockDim.x) {
        int l = idx >> 6, r = idx & 63;
        sh[r * 65 + l] = src[idx];          // coalesced read
    }
    __syncthreads();
    for (int idx = threadIdx.x; idx < 4096; idx += blockDim.x) {
        int r = idx >> 6, l = idx & 63;
        dst[idx] = sh[r * 65 + l];          // coalesced write
    }
}

// ============================================================
// Kernel 2: vector chains. One warp = one (batch, half) chain.
// Block = 4 warps of the SAME half marching in lockstep -> L1 tile reuse.
// grid = (32 batch-groups, 2 halves), 128 threads.
//
// Per site, lane k owns outputs o0=2k, o0+1. Tile row j holds pairs
// (c0[j][o], c1[j][o]); one LDG.128 per (row, lane) gives both outputs'
// pairs. State kept duplicated in shared as (v,v) so LDS.128 feeds
// fma.rn.f32x2 directly (no packing MOVs).
// ============================================================
__global__ void __launch_bounds__(128) chain_kernel(
    const float* __restrict__ x,      // [B][S][2]
    const float* __restrict__ cores,  // [S][l][r][i]
    const float* __restrict__ lvec,
    const float* __restrict__ rvec)
{
    __shared__ __align__(16) float2 sdup[4][64];
    const int wid  = threadIdx.x >> 5;
    const int lane = threadIdx.x & 31;
    const int half = blockIdx.y;
    const int batch = blockIdx.x * 4 + wid;
    const int o0 = 2 * lane;

    // init state = boundary vector (duplicated)
    const float* bv = half ? rvec : lvec;
    float bv0 = bv[o0], bv1 = bv[o0 + 1];
    sdup[wid][o0]     = make_float2(bv0, bv0);
    sdup[wid][o0 + 1] = make_float2(bv1, bv1);
    __syncwarp();

    const ulonglong2* Tb = half ? (const ulonglong2*)g_ct
                                : (const ulonglong2*)cores;

    for (int t = 0; t < HALFS; ++t) {
        const int s = half ? (255 - t) : t;
        const float2 xv = *(const float2*)(x + ((size_t)batch * SITES + s) * 2);
        const ulonglong2* T = Tb + (size_t)t * 2048 + lane; // 2048 u64x2 per site tile

        unsigned long long a0 = 0ull, a1 = 0ull, b0 = 0ull, b1 = 0ull;
        #pragma unroll
        for (int j = 0; j < 64; j += 2) {
            ulonglong2 ca = __ldg(&T[(size_t)j * 32]);       // row j:  pairs for o0, o0+1
            ulonglong2 cb = __ldg(&T[(size_t)(j + 1) * 32]); // row j+1
            ulonglong2 vv = *(const ulonglong2*)(&sdup[wid][j]); // (vj,vj, vj1,vj1) broadcast
            a0 = ffma2(ca.x, vv.x, a0);
            a1 = ffma2(ca.y, vv.x, a1);
            b0 = ffma2(cb.x, vv.y, b0);
            b1 = ffma2(cb.y, vv.y, b1);
        }
        a0 = fadd2(a0, b0);  // (feat0 dot, feat1 dot) for output o0
        a1 = fadd2(a1, b1);  // ... for output o0+1

        const float old0 = sdup[wid][o0].x;
        const float old1 = sdup[wid][o0 + 1].x;
        const float n0 = fmaf(xv.x, f2lo(a0), fmaf(xv.y, f2hi(a0), old0));
        const float n1 = fmaf(xv.x, f2lo(a1), fmaf(xv.y, f2hi(a1), old1));

        __syncwarp();  // all lanes finished reading old state
        *(float4*)(&sdup[wid][o0]) = make_float4(n0, n0, n1, n1);
        __syncwarp();  // new state visible before next site's reads

        if ((t & 3) == 3) __syncthreads(); // keep the 4 warps within an L1-sized window
    }

    float* dst = half ? g_wR : g_vL;
    dst[batch * 64 + o0]     = sdup[wid][o0].x;
    dst[batch * 64 + o0 + 1] = sdup[wid][o0 + 1].x;
}

// ============================================================
// Kernel 3: logits[b][o] = sum_{l,r} vL[l] * oc[o][l][r] * wR[r]
// ============================================================
__global__ void __launch_bounds__(64) combine_kernel(
    const float* __restrict__ oc, float* __restrict__ out)
{
    const int b = blockIdx.x;
    const int tid = threadIdx.x; // 0..63 = r
    __shared__ float vL[64], wR[64];
    __shared__ float red[2];
    vL[tid] = g_vL[b * 64 + tid];
    wR[tid] = g_wR[b * 64 + tid];
    __syncthreads();
    const float w = wR[tid];
    for (int o = 0; o < NOUT; ++o) {
        float acc = 0.f;
        const float* row = oc + (size_t)o * 4096 + tid;
        #pragma unroll 16
        for (int l = 0; l < 64; ++l)
            acc = fmaf(vL[l], row[(size_t)l * 64], acc);
        float p = acc * w;
        #pragma unroll
        for (int off = 16; off; off >>= 1)
            p += __shfl_down_sync(0xffffffffu, p, off);
        if ((tid & 31) == 0) red[tid >> 5] = p;
        __syncthreads();
        if (tid == 0) out[b * NOUT + o] = red[0] + red[1];
        __syncthreads();
    }
}

extern "C" void kernel_launch(void* const* d_in, const int* in_sizes, int n_in,
                              void* d_out, int out_size) {
    const float* input_data = (const float*)d_in[0]; // [128,256,2]
    const float* cores      = (const float*)d_in[1]; // [256,64,64,2]
    const float* out_core   = (const float*)d_in[2]; // [10,64,64]
    const float* lvec       = (const float*)d_in[3]; // [64]
    const float* rvec       = (const float*)d_in[4]; // [64]
    float* out = (float*)d_out;                      // [128,10]

    repack_kernel<<<HALFS, 256>>>(cores);
    chain_kernel<<<dim3(32, 2), 128>>>(input_data, cores, lvec, rvec);
    combine_kernel<<<BATCH, 64>>>(out_core, out);
}

// round 4
// speedup vs baseline: 5.2705x; 5.2705x over previous
#include <cuda_runtime.h>

#define BATCH 128
#define SITES 256
#define BOND 64
#define NOUT 10
#define HALFS 128          // sites per half
#define TILE_BYTES 32768   // 64*64*2 floats per site
#define STAGES 4

// Scratch (device globals — no allocation allowed)
__device__ __align__(16) float g_ct[HALFS * BOND * BOND * 2]; // right half, transposed+reversed
__device__ float g_vL[BATCH * BOND];
__device__ float g_wR[BATCH * BOND];

// ---- packed f32x2 helpers ----
static __device__ __forceinline__ unsigned long long ffma2(
    unsigned long long a, unsigned long long b, unsigned long long c) {
    unsigned long long d;
    asm("fma.rn.f32x2 %0, %1, %2, %3;" : "=l"(d) : "l"(a), "l"(b), "l"(c));
    return d;
}
static __device__ __forceinline__ unsigned long long fadd2(
    unsigned long long a, unsigned long long b) {
    unsigned long long d;
    asm("add.rn.f32x2 %0, %1, %2;" : "=l"(d) : "l"(a), "l"(b));
    return d;
}
static __device__ __forceinline__ float f2lo(unsigned long long v) {
    return __uint_as_float((unsigned)(v & 0xffffffffull));
}
static __device__ __forceinline__ float f2hi(unsigned long long v) {
    return __uint_as_float((unsigned)(v >> 32));
}
static __device__ __forceinline__ unsigned smem_u32(const void* p) {
    return (unsigned)__cvta_generic_to_shared(p);
}

// ---- mbarrier / bulk-copy primitives ----
static __device__ __forceinline__ void mbar_init(unsigned addr, unsigned count) {
    asm volatile("mbarrier.init.shared.b64 [%0], %1;" :: "r"(addr), "r"(count) : "memory");
}
static __device__ __forceinline__ void mbar_expect_tx(unsigned addr, unsigned bytes) {
    asm volatile("mbarrier.arrive.expect_tx.shared.b64 _, [%0], %1;"
                 :: "r"(addr), "r"(bytes) : "memory");
}
static __device__ __forceinline__ void mbar_wait(unsigned addr, unsigned parity) {
    asm volatile(
        "{\n\t"
        ".reg .pred P;\n\t"
        "WAIT_%=:\n\t"
        "mbarrier.try_wait.parity.acquire.cta.shared::cta.b64 P, [%0], %1, 0x989680;\n\t"
        "@P bra.uni DONE_%=;\n\t"
        "bra.uni WAIT_%=;\n\t"
        "DONE_%=:\n\t"
        "}"
        :: "r"(addr), "r"(parity) : "memory");
}
static __device__ __forceinline__ void bulk_g2s(unsigned dst, const void* src,
                                                unsigned bytes, unsigned mbar) {
    asm volatile(
        "cp.async.bulk.shared::cluster.global.mbarrier::complete_tx::bytes [%0], [%1], %2, [%3];"
        :: "r"(dst), "l"(src), "r"(bytes), "r"(mbar) : "memory");
}

// ============================================================
// Kernel 1: repack right-half cores.
// g_ct[t][r][2l+i] = cores[255 - t][l][r][i]
// ============================================================
__global__ void __launch_bounds__(256) repack_kernel(const float* __restrict__ cores) {
    int t = blockIdx.x;            // 0..127
    int s = 255 - t;
    __shared__ float2 sh[64 * 65];
    const float2* src = (const float2*)cores + (size_t)s * 4096; // [l*64 + r] -> (c0,c1)
    float2* dst = (float2*)g_ct + (size_t)t * 4096;              // [r*64 + l]
    for (int idx = threadIdx.x; idx < 4096; idx += blockDim.x) {
        int l = idx >> 6, r = idx & 63;
        sh[r * 65 + l] = src[idx];
    }
    __syncthreads();
    for (int idx = threadIdx.x; idx < 4096; idx += blockDim.x) {
        int r = idx >> 6, l = idx & 63;
        dst[idx] = sh[r * 65 + l];
    }
}

// ============================================================
// Kernel 2: vector chains, pipelined through shared memory.
// grid (32, 2): 32 batch-groups x 2 halves. 64 threads = 2 warps.
// Each warp handles 2 batch chains (register-blocked); tile for the
// current site lives in a 4-deep cp.async.bulk double... quad-buffer,
// so global latency is fully overlapped with the dependent recurrence.
// Lane owns outputs o0=2*lane, o0+1 for both of its batches.
// ============================================================
__global__ void __launch_bounds__(64) chain_kernel(
    const float* __restrict__ x,      // [B][S][2]
    const float* __restrict__ cores,  // [S][l][r][2]
    const float* __restrict__ lvec,
    const float* __restrict__ rvec)
{
    extern __shared__ __align__(128) char dynsmem[];   // STAGES * 32KB tile ring
    __shared__ __align__(16) float2 st[2][2][64];      // [warp][batch][j] = (v,v)
    __shared__ __align__(16) float2 sx[2][2][HALFS];   // per-chain x pairs, site order
    __shared__ __align__(8) unsigned long long mbar_store[STAGES];

    const int tid  = threadIdx.x;
    const int wid  = tid >> 5;
    const int lane = tid & 31;
    const int half = blockIdx.y;
    const int o0   = 2 * lane;

    unsigned mb[STAGES];
    #pragma unroll
    for (int s = 0; s < STAGES; ++s) mb[s] = smem_u32(&mbar_store[s]);

    if (tid == 0) {
        #pragma unroll
        for (int s = 0; s < STAGES; ++s) mbar_init(mb[s], 1);
    }

    // Stage per-chain x values into shared (site order t).
    for (int i = tid; i < 4 * HALFS; i += 64) {
        int b = i >> 7;          // 0..3 local chain
        int t = i & 127;
        int batch = blockIdx.x * 4 + b;
        int s = half ? (255 - t) : t;
        sx[b >> 1][b & 1][t] = *(const float2*)(x + ((size_t)batch * SITES + s) * 2);
    }
    // State init = boundary vector, duplicated (v,v).
    const float* bv = half ? rvec : lvec;
    for (int i = tid; i < 256; i += 64) {
        int w = i >> 7, b = (i >> 6) & 1, j = i & 63;
        float v = bv[j];
        st[w][b][j] = make_float2(v, v);
    }
    __syncthreads();

    const char* gsrc = half ? (const char*)g_ct : (const char*)cores;

    // Prime the pipeline.
    if (tid == 0) {
        #pragma unroll
        for (int s = 0; s < STAGES; ++s) {
            mbar_expect_tx(mb[s], TILE_BYTES);
            bulk_g2s(smem_u32(dynsmem + (size_t)s * TILE_BYTES),
                     gsrc + (size_t)s * TILE_BYTES, TILE_BYTES, mb[s]);
        }
    }

    for (int t = 0; t < HALFS; ++t) {
        const int s = t & (STAGES - 1);
        mbar_wait(mb[s], (t >> 2) & 1);

        const ulonglong2* tp = (const ulonglong2*)(dynsmem + (size_t)s * TILE_BYTES) + lane;

        unsigned long long a0A = 0, a1A = 0, b0A = 0, b1A = 0;
        unsigned long long a0B = 0, a1B = 0, b0B = 0, b1B = 0;
        #pragma unroll 8
        for (int j = 0; j < 64; j += 2) {
            ulonglong2 ca = tp[j * 32];        // row j   pairs for outputs o0, o0+1
            ulonglong2 cb = tp[j * 32 + 32];   // row j+1
            ulonglong2 uA = *(const ulonglong2*)&st[wid][0][j]; // (vj,vj | vj+1,vj+1)
            ulonglong2 uB = *(const ulonglong2*)&st[wid][1][j];
            a0A = ffma2(ca.x, uA.x, a0A); a1A = ffma2(ca.y, uA.x, a1A);
            b0A = ffma2(cb.x, uA.y, b0A); b1A = ffma2(cb.y, uA.y, b1A);
            a0B = ffma2(ca.x, uB.x, a0B); a1B = ffma2(ca.y, uB.x, a1B);
            b0B = ffma2(cb.x, uB.y, b0B); b1B = ffma2(cb.y, uB.y, b1B);
        }
        a0A = fadd2(a0A, b0A); a1A = fadd2(a1A, b1A);
        a0B = fadd2(a0B, b0B); a1B = fadd2(a1B, b1B);

        const float2 xA = sx[wid][0][t];
        const float2 xB = sx[wid][1][t];
        const float oA0 = st[wid][0][o0].x, oA1 = st[wid][0][o0 + 1].x;
        const float oB0 = st[wid][1][o0].x, oB1 = st[wid][1][o0 + 1].x;
        const float n0A = fmaf(xA.x, f2lo(a0A), fmaf(xA.y, f2hi(a0A), oA0));
        const float n1A = fmaf(xA.x, f2lo(a1A), fmaf(xA.y, f2hi(a1A), oA1));
        const float n0B = fmaf(xB.x, f2lo(a0B), fmaf(xB.y, f2hi(a0B), oB0));
        const float n1B = fmaf(xB.x, f2lo(a1B), fmaf(xB.y, f2hi(a1B), oB1));

        __syncwarp();  // all lanes done reading old state
        *(float4*)&st[wid][0][o0] = make_float4(n0A, n0A, n1A, n1A);
        *(float4*)&st[wid][1][o0] = make_float4(n0B, n0B, n1B, n1B);

        __syncthreads(); // both warps done with stage s; new state visible

        if (tid == 0 && t + STAGES < HALFS) {
            mbar_expect_tx(mb[s], TILE_BYTES);
            bulk_g2s(smem_u32(dynsmem + (size_t)s * TILE_BYTES),
                     gsrc + (size_t)(t + STAGES) * TILE_BYTES, TILE_BYTES, mb[s]);
        }
    }

    float* dst = half ? g_wR : g_vL;
    const int batchA = blockIdx.x * 4 + wid * 2;
    dst[batchA * 64 + o0]           = st[wid][0][o0].x;
    dst[batchA * 64 + o0 + 1]       = st[wid][0][o0 + 1].x;
    dst[(batchA + 1) * 64 + o0]     = st[wid][1][o0].x;
    dst[(batchA + 1) * 64 + o0 + 1] = st[wid][1][o0 + 1].x;
}

// ============================================================
// Kernel 3: logits[b][o] = sum_{l,r} vL[l] * oc[o][l][r] * wR[r]
// ============================================================
__global__ void __launch_bounds__(64) combine_kernel(
    const float* __restrict__ oc, float* __restrict__ out)
{
    const int b = blockIdx.x;
    const int tid = threadIdx.x; // 0..63 = r
    __shared__ float vL[64], wR[64];
    __shared__ float red[2];
    vL[tid] = g_vL[b * 64 + tid];
    wR[tid] = g_wR[b * 64 + tid];
    __syncthreads();
    const float w = wR[tid];
    for (int o = 0; o < NOUT; ++o) {
        float acc = 0.f;
        const float* row = oc + (size_t)o * 4096 + tid;
        #pragma unroll 16
        for (int l = 0; l < 64; ++l)
            acc = fmaf(vL[l], row[(size_t)l * 64], acc);
        float p = acc * w;
        #pragma unroll
        for (int off = 16; off; off >>= 1)
            p += __shfl_down_sync(0xffffffffu, p, off);
        if ((tid & 31) == 0) red[tid >> 5] = p;
        __syncthreads();
        if (tid == 0) out[b * NOUT + o] = red[0] + red[1];
        __syncthreads();
    }
}

extern "C" void kernel_launch(void* const* d_in, const int* in_sizes, int n_in,
                              void* d_out, int out_size) {
    const float* input_data = (const float*)d_in[0]; // [128,256,2]
    const float* cores      = (const float*)d_in[1]; // [256,64,64,2]
    const float* out_core   = (const float*)d_in[2]; // [10,64,64]
    const float* lvec       = (const float*)d_in[3]; // [64]
    const float* rvec       = (const float*)d_in[4]; // [64]
    float* out = (float*)d_out;                      // [128,10]

    cudaFuncSetAttribute(chain_kernel,
                         cudaFuncAttributeMaxDynamicSharedMemorySize,
                         STAGES * TILE_BYTES);

    repack_kernel<<<HALFS, 256>>>(cores);
    chain_kernel<<<dim3(32, 2), 64, STAGES * TILE_BYTES>>>(input_data, cores, lvec, rvec);
    combine_kernel<<<BATCH, 64>>>(out_core, out);
}